// round 10
// baseline (speedup 1.0000x reference)
#include <cuda_runtime.h>

// Input:  x  (B=64, C=3, H=512, W+1=513) fp32; h_orig = x[b,0,0,512], w_orig = x[b,1,0,512]
// Output: (64, 3, 224, 224) fp32
// Resize shorter side to 256 (bilinear, half-pixel centers, rint), center-crop 224x224.
// R7: shared-memory row staging. One block = one output row of one image.
// Stage the needed span of 2 input rows x 3 channels with coalesced loads,
// then bilinear-interp from smem.

#define OUT_H 224
#define OUT_W 224
#define IN_H 512
#define IN_W_STRIDE 513
#define PLANE (IN_H * IN_W_STRIDE)
#define RESIZE_TO 256.0f

#define SPAN 452              // max tap span per row: 223*2.004 + 2 < 452
#define SSTRIDE 456           // padded stride (16B aligned)
#define NPLANES 6             // 3 channels x 2 input rows
#define STAGE_TOTAL (NPLANES * SPAN)   // 2712 elements

__global__ __launch_bounds__(OUT_W) void center_crop_kernel(
    const float* __restrict__ x, float* __restrict__ out)
{
    __shared__ float s[NPLANES * SSTRIDE];

    const int y = blockIdx.x;   // output row 0..223
    const int b = blockIdx.y;   // image 0..63
    const int tx = threadIdx.x; // output col 0..223

    const float* img = x + b * (3 * PLANE);

    // ---- per-image params (same value in every thread) ----
    const float h = img[IN_W_STRIDE - 1];
    const float w = img[PLANE + IN_W_STRIDE - 1];
    const float min_dim = fminf(h, w);
    const float scale = RESIZE_TO / min_dim;
    const float h_res = rintf(h * scale);
    const float w_res = rintf(w * scale);
    const float top  = rintf((h_res - (float)OUT_H) * 0.5f);
    const float left = rintf((w_res - (float)OUT_W) * 0.5f);

    const int hi = (int)h - 1;
    const int wi = (int)w - 1;

    // ---- row coordinate (uniform across block) ----
    float src_y = (((float)y + top) + 0.5f) * h / h_res - 0.5f;
    src_y = fminf(fmaxf(src_y, 0.0f), h - 1.0f);
    const float y0f = floorf(src_y);
    const float wy = src_y - y0f;
    int y0 = (int)y0f;
    y0 = max(0, min(y0, hi));
    const int y1 = min(y0 + 1, hi);   // staged row B

    // ---- column coordinate (per thread) ----
    const float inv_wres = w / w_res;
    float src_x = (((float)tx + left) + 0.5f) * inv_wres - 0.5f;
    src_x = fminf(fmaxf(src_x, 0.0f), w - 1.0f);
    const float x0f = floorf(src_x);
    const float wx = src_x - x0f;
    int x0 = (int)x0f;
    x0 = max(0, min(x0, wi));

    // x_first = x0 at tx==0 (monotone in tx, so this is the block minimum)
    float sx0 = ((left) + 0.5f) * inv_wres - 0.5f;
    sx0 = fminf(fmaxf(sx0, 0.0f), w - 1.0f);
    int x_first = (int)floorf(sx0);
    x_first = max(0, min(x_first, wi));

    // ---- stage: 6 planes (ch-major, rowA then rowB) of SPAN floats ----
    const int rowA = y0 * IN_W_STRIDE;
    const int rowB = y1 * IN_W_STRIDE;
    #pragma unroll
    for (int i = tx; i < STAGE_TOTAL; i += OUT_W) {
        const int p = i / SPAN;        // 0..5
        const int j = i - p * SPAN;    // 0..451
        const int ch = p >> 1;
        const int rowoff = (p & 1) ? rowB : rowA;
        const int gx = min(x_first + j, wi);   // right-edge clamp baked in
        s[p * SSTRIDE + j] = __ldg(img + ch * PLANE + rowoff + gx);
    }
    __syncthreads();

    // ---- bilinear from smem ----
    const int j0 = x0 - x_first;       // staged[j0+1] is always the x1 tap
    const int out_base = b * (3 * OUT_H * OUT_W) + y * OUT_W + tx;

    #pragma unroll
    for (int c = 0; c < 3; c++) {
        const float* sa = s + (2 * c) * SSTRIDE + j0;
        const float* sb = s + (2 * c + 1) * SSTRIDE + j0;
        const float v00 = sa[0], v01 = sa[1];
        const float v10 = sb[0], v11 = sb[1];
        const float t0 = v00 + wx * (v01 - v00);
        const float t1 = v10 + wx * (v11 - v10);
        const float res = t0 + wy * (t1 - t0);
        out[out_base + c * (OUT_H * OUT_W)] = res;
    }
}

extern "C" void kernel_launch(void* const* d_in, const int* in_sizes, int n_in,
                              void* d_out, int out_size)
{
    const float* x = (const float*)d_in[0];
    float* out = (float*)d_out;
    dim3 grid(OUT_H, 64);
    dim3 block(OUT_W);
    center_crop_kernel<<<grid, block>>>(x, out);
}